// round 1
// baseline (speedup 1.0000x reference)
#include <cuda_runtime.h>
#include <cstdint>

// Problem constants
#define B_   32
#define CIN  1024
#define COUT 512
#define NSP  1568          // T*H*W = 8*14*14
#define NHEAD 8
#define DK   64

// Scratch buffers (device globals: allocation-free contract)
__device__ float g_k[(size_t)B_ * COUT * NSP];
__device__ float g_q[(size_t)B_ * COUT * NSP];
__device__ float g_v[(size_t)B_ * COUT * NSP];
__device__ float g_o[(size_t)B_ * COUT * NSP];

// ---------------------------------------------------------------------------
// GEMM: Y[b, m, n] = sum_k W[m, k] * X[b, k, n] + bias[m]
// BM=BN=128, BK=8, 256 threads, 8x8 microtile (split 4+4 fragments).
// M % 128 == 0, K % 8 == 0 assumed (holds: 512/1024, 1024/512). N guarded.
// ---------------------------------------------------------------------------
__global__ void __launch_bounds__(256)
gemm_bias_kernel(const float* __restrict__ W, const float* __restrict__ X,
                 const float* __restrict__ bias, float* __restrict__ Y,
                 int M, int N, int K)
{
    __shared__ float As[8][128];
    __shared__ float Bs[8][128];

    const int tid = threadIdx.x;
    const int tx = tid & 15;        // column-group id
    const int ty = tid >> 4;        // row-group id
    const int m0 = blockIdx.y * 128;
    const int n0 = blockIdx.x * 128;
    const int b  = blockIdx.z;

    const float* Xb = X + (size_t)b * K * N;
    float*       Yb = Y + (size_t)b * (size_t)M * N;

    float acc[8][8];
#pragma unroll
    for (int i = 0; i < 8; i++)
#pragma unroll
        for (int j = 0; j < 8; j++) acc[i][j] = 0.f;

    // A-load: 128 rows x 8 k  -> thread (tid>>1, (tid&1)*4) loads one float4 along k
    const int am = tid >> 1;
    const int ak = (tid & 1) << 2;
    // B-load: 8 k x 128 n     -> thread (tid>>5, (tid&31)*4) loads one float4 along n
    const int bk = tid >> 5;
    const int bn = (tid & 31) << 2;

    const float* Wp = W + (size_t)(m0 + am) * K + ak;
    const bool bvalid = (n0 + bn) < N;

    for (int k0 = 0; k0 < K; k0 += 8) {
        float4 a = *(const float4*)(Wp + k0);
        As[ak + 0][am] = a.x;
        As[ak + 1][am] = a.y;
        As[ak + 2][am] = a.z;
        As[ak + 3][am] = a.w;

        float4 bv = make_float4(0.f, 0.f, 0.f, 0.f);
        if (bvalid) bv = *(const float4*)&Xb[(size_t)(k0 + bk) * N + n0 + bn];
        *(float4*)&Bs[bk][bn] = bv;

        __syncthreads();

#pragma unroll
        for (int kk = 0; kk < 8; kk++) {
            float ar[8], br[8];
            *(float4*)&ar[0] = *(const float4*)&As[kk][ty * 4];
            *(float4*)&ar[4] = *(const float4*)&As[kk][64 + ty * 4];
            *(float4*)&br[0] = *(const float4*)&Bs[kk][tx * 4];
            *(float4*)&br[4] = *(const float4*)&Bs[kk][64 + tx * 4];
#pragma unroll
            for (int i = 0; i < 8; i++)
#pragma unroll
                for (int j = 0; j < 8; j++)
                    acc[i][j] += ar[i] * br[j];
        }
        __syncthreads();
    }

    // Epilogue: add bias, guarded float4 stores (N % 4 == 0)
#pragma unroll
    for (int i = 0; i < 8; i++) {
        const int m = m0 + ((i < 4) ? (ty * 4 + i) : (64 + ty * 4 + (i - 4)));
        const float bb = bias[m];
        const int n1 = n0 + tx * 4;
        const int n2 = n0 + 64 + tx * 4;
        if (n1 < N) {
            float4 o;
            o.x = acc[i][0] + bb; o.y = acc[i][1] + bb;
            o.z = acc[i][2] + bb; o.w = acc[i][3] + bb;
            *(float4*)&Yb[(size_t)m * N + n1] = o;
        }
        if (n2 < N) {
            float4 o;
            o.x = acc[i][4] + bb; o.y = acc[i][5] + bb;
            o.z = acc[i][6] + bb; o.w = acc[i][7] + bb;
            *(float4*)&Yb[(size_t)m * N + n2] = o;
        }
    }
}

// ---------------------------------------------------------------------------
// Attention per (b, h). K/Q/V read from flat projection buffers with the
// torch-view layout: row n of head h is 64 contiguous floats at n*512 + h*64.
// S[i][j] = sum_n K[n,i]*Q[n,j] / 8 ; softmax over j ;
// O[i][n] = sum_j P[i][j]*V[n,j], written to channel o2 = i*8 + h.
// 1568 = 49 * 32 (exact chunking).
// ---------------------------------------------------------------------------
__global__ void __launch_bounds__(256)
attention_kernel(const float* __restrict__ Kp, const float* __restrict__ Qp,
                 const float* __restrict__ Vp, float* __restrict__ Op)
{
    const int bh = blockIdx.x;
    const int b = bh >> 3;
    const int h = bh & 7;
    const size_t base = (size_t)b * (COUT * NSP);

    const float* Kb = Kp + base + h * DK;
    const float* Qb = Qp + base + h * DK;
    const float* Vb = Vp + base + h * DK;
    float*       Ob = Op + base;

    __shared__ float Ks[32][65];
    __shared__ float Qs[32][65];
    __shared__ float Vs[32][65];
    __shared__ float Ss[64][65];

    const int tid = threadIdx.x;
    const int tx = tid & 15;
    const int ty = tid >> 4;

    float acc[4][4];
#pragma unroll
    for (int i = 0; i < 4; i++)
#pragma unroll
        for (int j = 0; j < 4; j++) acc[i][j] = 0.f;

    // -------- Phase 1: S = K^T Q --------
    for (int nb = 0; nb < NSP; nb += 32) {
#pragma unroll
        for (int u = 0; u < 2; u++) {
            const int idx = tid + u * 256;     // 0..511
            const int r = idx >> 4;            // 0..31
            const int c = (idx & 15) << 2;     // 0..60
            const size_t g = (size_t)(nb + r) * COUT + c;
            float4 kv = *(const float4*)&Kb[g];
            Ks[r][c + 0] = kv.x; Ks[r][c + 1] = kv.y;
            Ks[r][c + 2] = kv.z; Ks[r][c + 3] = kv.w;
            float4 qv = *(const float4*)&Qb[g];
            Qs[r][c + 0] = qv.x; Qs[r][c + 1] = qv.y;
            Qs[r][c + 2] = qv.z; Qs[r][c + 3] = qv.w;
        }
        __syncthreads();
#pragma unroll
        for (int n = 0; n < 32; n++) {
            float ar[4], br[4];
#pragma unroll
            for (int i = 0; i < 4; i++) ar[i] = Ks[n][ty * 4 + i];
#pragma unroll
            for (int j = 0; j < 4; j++) br[j] = Qs[n][tx * 4 + j];
#pragma unroll
            for (int i = 0; i < 4; i++)
#pragma unroll
                for (int j = 0; j < 4; j++)
                    acc[i][j] += ar[i] * br[j];
        }
        __syncthreads();
    }

    // Stage S (scaled by 1/sqrt(dk) = 1/8) into smem
#pragma unroll
    for (int i = 0; i < 4; i++)
#pragma unroll
        for (int j = 0; j < 4; j++)
            Ss[ty * 4 + i][tx * 4 + j] = acc[i][j] * 0.125f;
    __syncthreads();

    // -------- Softmax over j, one thread per row --------
    if (tid < 64) {
        float mx = -1e30f;
#pragma unroll 8
        for (int j = 0; j < 64; j++) mx = fmaxf(mx, Ss[tid][j]);
        float sum = 0.f;
#pragma unroll 8
        for (int j = 0; j < 64; j++) {
            float e = expf(Ss[tid][j] - mx);
            Ss[tid][j] = e;
            sum += e;
        }
        const float inv = 1.0f / sum;
#pragma unroll 8
        for (int j = 0; j < 64; j++) Ss[tid][j] *= inv;
    }
    __syncthreads();

    // -------- Phase 2: O[i][n] = sum_j P[i][j] * V[n][j] --------
    for (int nb = 0; nb < NSP; nb += 32) {
#pragma unroll
        for (int u = 0; u < 2; u++) {
            const int idx = tid + u * 256;
            const int r = idx >> 4;
            const int c = (idx & 15) << 2;
            float4 vv = *(const float4*)&Vb[(size_t)(nb + r) * COUT + c];
            Vs[r][c + 0] = vv.x; Vs[r][c + 1] = vv.y;
            Vs[r][c + 2] = vv.z; Vs[r][c + 3] = vv.w;
        }
        __syncthreads();

        float o[4][2];
#pragma unroll
        for (int i = 0; i < 4; i++) { o[i][0] = 0.f; o[i][1] = 0.f; }
#pragma unroll
        for (int j = 0; j < 64; j++) {
            const float v0 = Vs[tx][j];        // n = nb + tx
            const float v1 = Vs[16 + tx][j];   // n = nb + 16 + tx
#pragma unroll
            for (int i = 0; i < 4; i++) {
                const float p = Ss[ty * 4 + i][j];
                o[i][0] += p * v0;
                o[i][1] += p * v1;
            }
        }
#pragma unroll
        for (int i = 0; i < 4; i++) {
            const int o2 = (ty * 4 + i) * NHEAD + h;   // output channel after torch transpose+view
            Ob[(size_t)o2 * NSP + nb + tx]      = o[i][0];
            Ob[(size_t)o2 * NSP + nb + 16 + tx] = o[i][1];
        }
        __syncthreads();
    }
}

// ---------------------------------------------------------------------------
// Launch
// Inputs (metadata order): x, query, key_w, key_b, query_w, query_b,
//                          val_w, val_b, up_w, up_b
// ---------------------------------------------------------------------------
extern "C" void kernel_launch(void* const* d_in, const int* in_sizes, int n_in,
                              void* d_out, int out_size)
{
    const float* x       = (const float*)d_in[0];
    const float* query   = (const float*)d_in[1];
    const float* key_w   = (const float*)d_in[2];
    const float* key_b   = (const float*)d_in[3];
    const float* query_w = (const float*)d_in[4];
    const float* query_b = (const float*)d_in[5];
    const float* val_w   = (const float*)d_in[6];
    const float* val_b   = (const float*)d_in[7];
    const float* up_w    = (const float*)d_in[8];
    const float* up_b    = (const float*)d_in[9];
    float* out = (float*)d_out;

    float *kbuf, *qbuf, *vbuf, *obuf;
    cudaGetSymbolAddress((void**)&kbuf, g_k);
    cudaGetSymbolAddress((void**)&qbuf, g_q);
    cudaGetSymbolAddress((void**)&vbuf, g_v);
    cudaGetSymbolAddress((void**)&obuf, g_o);

    const dim3 blk(256);
    const dim3 grid_proj((NSP + 127) / 128, COUT / 128, B_);   // (13, 4, 32)
    const dim3 grid_up((NSP + 127) / 128, CIN / 128, B_);      // (13, 8, 32)

    // Projections
    gemm_bias_kernel<<<grid_proj, blk>>>(key_w,   x,     key_b,   kbuf, COUT, NSP, CIN);
    gemm_bias_kernel<<<grid_proj, blk>>>(query_w, query, query_b, qbuf, COUT, NSP, CIN);
    gemm_bias_kernel<<<grid_proj, blk>>>(val_w,   x,     val_b,   vbuf, COUT, NSP, CIN);

    // Attention: one block per (batch, head)
    attention_kernel<<<B_ * NHEAD, blk>>>(kbuf, qbuf, vbuf, obuf);

    // Up projection -> output
    gemm_bias_kernel<<<grid_up, blk>>>(up_w, obuf, up_b, out, CIN, NSP, COUT);
}

// round 2
// speedup vs baseline: 2.9207x; 2.9207x over previous
#include <cuda_runtime.h>
#include <cstdint>

// Problem constants
#define B_   32
#define CIN  1024
#define COUT 512
#define NSP  1568          // T*H*W = 8*14*14
#define NHEAD 8
#define DK   64

// Scratch buffers (device globals: allocation-free contract)
__device__ float g_k[(size_t)B_ * COUT * NSP];
__device__ float g_q[(size_t)B_ * COUT * NSP];
__device__ float g_v[(size_t)B_ * COUT * NSP];
__device__ float g_o[(size_t)B_ * COUT * NSP];

// ---------------------------------------------------------------------------
// TF32 helpers
// ---------------------------------------------------------------------------
__device__ __forceinline__ uint32_t f2tf(float x) {
    uint32_t r;
    asm("cvt.rna.tf32.f32 %0, %1;" : "=r"(r) : "f"(x));
    return r;
}

__device__ __forceinline__ void mma8(float* d, const uint32_t* a, const uint32_t* b) {
    asm volatile(
        "mma.sync.aligned.m16n8k8.row.col.f32.tf32.tf32.f32 "
        "{%0,%1,%2,%3},{%4,%5,%6,%7},{%8,%9},{%0,%1,%2,%3};"
        : "+f"(d[0]), "+f"(d[1]), "+f"(d[2]), "+f"(d[3])
        : "r"(a[0]), "r"(a[1]), "r"(a[2]), "r"(a[3]), "r"(b[0]), "r"(b[1]));
}

// ---------------------------------------------------------------------------
// TF32 tensor-core GEMM: Y[b, m, n] = sum_k W[m,k] * X[b,k,n] + bias[m]
// BM=BN=128, BK=16, 256 threads (8 warps, 2x4), warp tile 64x32.
// Double-buffered smem, one __syncthreads per K-step.
// k-permutation: frag-col c <-> k=2c, frag-col c+4 <-> k=2c+1 (applied to
// both A and B, so results are exact) => contiguous float2 A-fragment loads.
// M % 128 == 0, K % 16 == 0 assumed. N guarded (N % 4 == 0).
// ---------------------------------------------------------------------------
#define AST 24    // As row stride (words): conflict-free LDS.64 frag loads
#define BST 132   // Bs row stride (words): conflict-free LDS.32 frag loads

__global__ void __launch_bounds__(256)
gemm_tf32_kernel(const float* __restrict__ W, const float* __restrict__ X,
                 const float* __restrict__ bias, float* __restrict__ Y,
                 int M, int N, int K)
{
    __shared__ uint32_t As[2][128][AST];
    __shared__ uint32_t Bs[2][16][BST];

    const int tid  = threadIdx.x;
    const int lane = tid & 31;
    const int wid  = tid >> 5;
    const int g    = lane >> 2;     // group id (0..7)
    const int c    = lane & 3;      // thread-in-group (0..3)
    const int wm   = (wid >> 2) * 64;   // warp m-offset: 0 / 64
    const int wn   = (wid & 3) * 32;    // warp n-offset: 0/32/64/96

    const int m0 = blockIdx.y * 128;
    const int n0 = blockIdx.x * 128;
    const int b  = blockIdx.z;
    const float* Xb = X + (size_t)b * K * N;
    float*       Yb = Y + (size_t)b * (size_t)M * N;

    // A LDG mapping: 128 rows x 16 k -> thread (tid>>2, (tid&3)*4), 2 rows apart by 64
    const int rowA = tid >> 2;          // 0..63
    const int kqA  = (tid & 3) << 2;    // 0,4,8,12
    // B LDG mapping: 16 k x 128 n -> thread (tid>>5, (tid&31)*4), 2 rows apart by 8
    const int kB = tid >> 5;            // 0..7
    const int nB = (tid & 31) << 2;     // 0..124
    const bool bval = (n0 + nB) < N;

    const float* Ap0 = W  + (size_t)(m0 + rowA) * K + kqA;
    const float* Ap1 = Ap0 + (size_t)64 * K;
    const float* Bp0 = Xb + (size_t)kB * N + n0 + nB;
    const float* Bp1 = Bp0 + (size_t)8 * N;

    float acc[4][4][4];
#pragma unroll
    for (int mt = 0; mt < 4; mt++)
#pragma unroll
        for (int nt = 0; nt < 4; nt++)
#pragma unroll
            for (int r = 0; r < 4; r++) acc[mt][nt][r] = 0.f;

    const int KT = K >> 4;

    float4 ar0, ar1, br0, br1;
    const float4 fz = make_float4(0.f, 0.f, 0.f, 0.f);

    // Prologue: load tile 0
    ar0 = *(const float4*)(Ap0);
    ar1 = *(const float4*)(Ap1);
    br0 = bval ? *(const float4*)(Bp0) : fz;
    br1 = bval ? *(const float4*)(Bp1) : fz;

    // STS tile 0 into buffer 0
    {
        uint4 u;
        u.x = f2tf(ar0.x); u.y = f2tf(ar0.y); u.z = f2tf(ar0.z); u.w = f2tf(ar0.w);
        *(uint4*)&As[0][rowA][kqA] = u;
        u.x = f2tf(ar1.x); u.y = f2tf(ar1.y); u.z = f2tf(ar1.z); u.w = f2tf(ar1.w);
        *(uint4*)&As[0][rowA + 64][kqA] = u;
        Bs[0][kB][nB + 0] = f2tf(br0.x); Bs[0][kB][nB + 1] = f2tf(br0.y);
        Bs[0][kB][nB + 2] = f2tf(br0.z); Bs[0][kB][nB + 3] = f2tf(br0.w);
        Bs[0][kB + 8][nB + 0] = f2tf(br1.x); Bs[0][kB + 8][nB + 1] = f2tf(br1.y);
        Bs[0][kB + 8][nB + 2] = f2tf(br1.z); Bs[0][kB + 8][nB + 3] = f2tf(br1.w);
    }
    __syncthreads();

    for (int kt = 0; kt < KT; kt++) {
        const int cur = kt & 1;

        if (kt + 1 < KT) {
            const int k0 = (kt + 1) << 4;
            ar0 = *(const float4*)(Ap0 + k0);
            ar1 = *(const float4*)(Ap1 + k0);
            br0 = bval ? *(const float4*)(Bp0 + (size_t)k0 * N) : fz;
            br1 = bval ? *(const float4*)(Bp1 + (size_t)k0 * N) : fz;
        }

        // Compute 2 x k8 steps from buffer cur
#pragma unroll
        for (int ks = 0; ks < 16; ks += 8) {
            uint32_t af[4][4];
#pragma unroll
            for (int mt = 0; mt < 4; mt++) {
                uint2 lo = *(const uint2*)&As[cur][wm + mt * 16 + g][ks + 2 * c];
                uint2 hi = *(const uint2*)&As[cur][wm + mt * 16 + 8 + g][ks + 2 * c];
                af[mt][0] = lo.x; af[mt][2] = lo.y;   // (row g,  k=2c / 2c+1)
                af[mt][1] = hi.x; af[mt][3] = hi.y;   // (row g+8)
            }
            uint32_t bf[4][2];
#pragma unroll
            for (int nt = 0; nt < 4; nt++) {
                bf[nt][0] = Bs[cur][ks + 2 * c][wn + nt * 8 + g];
                bf[nt][1] = Bs[cur][ks + 2 * c + 1][wn + nt * 8 + g];
            }
#pragma unroll
            for (int mt = 0; mt < 4; mt++)
#pragma unroll
                for (int nt = 0; nt < 4; nt++)
                    mma8(acc[mt][nt], af[mt], bf[nt]);
        }

        if (kt + 1 < KT) {
            const int nxt = cur ^ 1;
            uint4 u;
            u.x = f2tf(ar0.x); u.y = f2tf(ar0.y); u.z = f2tf(ar0.z); u.w = f2tf(ar0.w);
            *(uint4*)&As[nxt][rowA][kqA] = u;
            u.x = f2tf(ar1.x); u.y = f2tf(ar1.y); u.z = f2tf(ar1.z); u.w = f2tf(ar1.w);
            *(uint4*)&As[nxt][rowA + 64][kqA] = u;
            Bs[nxt][kB][nB + 0] = f2tf(br0.x); Bs[nxt][kB][nB + 1] = f2tf(br0.y);
            Bs[nxt][kB][nB + 2] = f2tf(br0.z); Bs[nxt][kB][nB + 3] = f2tf(br0.w);
            Bs[nxt][kB + 8][nB + 0] = f2tf(br1.x); Bs[nxt][kB + 8][nB + 1] = f2tf(br1.y);
            Bs[nxt][kB + 8][nB + 2] = f2tf(br1.z); Bs[nxt][kB + 8][nB + 3] = f2tf(br1.w);
            __syncthreads();
        }
    }

    // Epilogue: bias + guarded float2 stores
#pragma unroll
    for (int mt = 0; mt < 4; mt++) {
        const int mA = m0 + wm + mt * 16 + g;
        const float bb0 = bias[mA];
        const float bb1 = bias[mA + 8];
#pragma unroll
        for (int nt = 0; nt < 4; nt++) {
            const int n = n0 + wn + nt * 8 + 2 * c;
            if (n < N) {
                float2 o0, o1;
                o0.x = acc[mt][nt][0] + bb0; o0.y = acc[mt][nt][1] + bb0;
                o1.x = acc[mt][nt][2] + bb1; o1.y = acc[mt][nt][3] + bb1;
                *(float2*)&Yb[(size_t)mA * N + n]       = o0;
                *(float2*)&Yb[(size_t)(mA + 8) * N + n] = o1;
            }
        }
    }
}

// ---------------------------------------------------------------------------
// Attention per (b, h) — unchanged from R1 (fp32 SIMT, 297us total).
// ---------------------------------------------------------------------------
__global__ void __launch_bounds__(256)
attention_kernel(const float* __restrict__ Kp, const float* __restrict__ Qp,
                 const float* __restrict__ Vp, float* __restrict__ Op)
{
    const int bh = blockIdx.x;
    const int b = bh >> 3;
    const int h = bh & 7;
    const size_t base = (size_t)b * (COUT * NSP);

    const float* Kb = Kp + base + h * DK;
    const float* Qb = Qp + base + h * DK;
    const float* Vb = Vp + base + h * DK;
    float*       Ob = Op + base;

    __shared__ float Ks[32][65];
    __shared__ float Qs[32][65];
    __shared__ float Vs[32][65];
    __shared__ float Ss[64][65];

    const int tid = threadIdx.x;
    const int tx = tid & 15;
    const int ty = tid >> 4;

    float acc[4][4];
#pragma unroll
    for (int i = 0; i < 4; i++)
#pragma unroll
        for (int j = 0; j < 4; j++) acc[i][j] = 0.f;

    // -------- Phase 1: S = K^T Q --------
    for (int nb = 0; nb < NSP; nb += 32) {
#pragma unroll
        for (int u = 0; u < 2; u++) {
            const int idx = tid + u * 256;
            const int r = idx >> 4;
            const int cc = (idx & 15) << 2;
            const size_t gg = (size_t)(nb + r) * COUT + cc;
            float4 kv = *(const float4*)&Kb[gg];
            Ks[r][cc + 0] = kv.x; Ks[r][cc + 1] = kv.y;
            Ks[r][cc + 2] = kv.z; Ks[r][cc + 3] = kv.w;
            float4 qv = *(const float4*)&Qb[gg];
            Qs[r][cc + 0] = qv.x; Qs[r][cc + 1] = qv.y;
            Qs[r][cc + 2] = qv.z; Qs[r][cc + 3] = qv.w;
        }
        __syncthreads();
#pragma unroll
        for (int n = 0; n < 32; n++) {
            float ar[4], br[4];
#pragma unroll
            for (int i = 0; i < 4; i++) ar[i] = Ks[n][ty * 4 + i];
#pragma unroll
            for (int j = 0; j < 4; j++) br[j] = Qs[n][tx * 4 + j];
#pragma unroll
            for (int i = 0; i < 4; i++)
#pragma unroll
                for (int j = 0; j < 4; j++)
                    acc[i][j] += ar[i] * br[j];
        }
        __syncthreads();
    }

#pragma unroll
    for (int i = 0; i < 4; i++)
#pragma unroll
        for (int j = 0; j < 4; j++)
            Ss[ty * 4 + i][tx * 4 + j] = acc[i][j] * 0.125f;
    __syncthreads();

    if (tid < 64) {
        float mx = -1e30f;
#pragma unroll 8
        for (int j = 0; j < 64; j++) mx = fmaxf(mx, Ss[tid][j]);
        float sum = 0.f;
#pragma unroll 8
        for (int j = 0; j < 64; j++) {
            float e = expf(Ss[tid][j] - mx);
            Ss[tid][j] = e;
            sum += e;
        }
        const float inv = 1.0f / sum;
#pragma unroll 8
        for (int j = 0; j < 64; j++) Ss[tid][j] *= inv;
    }
    __syncthreads();

    // -------- Phase 2: O[i][n] = sum_j P[i][j] * V[n][j] --------
    for (int nb = 0; nb < NSP; nb += 32) {
#pragma unroll
        for (int u = 0; u < 2; u++) {
            const int idx = tid + u * 256;
            const int r = idx >> 4;
            const int cc = (idx & 15) << 2;
            float4 vv = *(const float4*)&Vb[(size_t)(nb + r) * COUT + cc];
            Vs[r][cc + 0] = vv.x; Vs[r][cc + 1] = vv.y;
            Vs[r][cc + 2] = vv.z; Vs[r][cc + 3] = vv.w;
        }
        __syncthreads();

        float o[4][2];
#pragma unroll
        for (int i = 0; i < 4; i++) { o[i][0] = 0.f; o[i][1] = 0.f; }
#pragma unroll
        for (int j = 0; j < 64; j++) {
            const float v0 = Vs[tx][j];
            const float v1 = Vs[16 + tx][j];
#pragma unroll
            for (int i = 0; i < 4; i++) {
                const float p = Ss[ty * 4 + i][j];
                o[i][0] += p * v0;
                o[i][1] += p * v1;
            }
        }
#pragma unroll
        for (int i = 0; i < 4; i++) {
            const int o2 = (ty * 4 + i) * NHEAD + h;
            Ob[(size_t)o2 * NSP + nb + tx]      = o[i][0];
            Ob[(size_t)o2 * NSP + nb + 16 + tx] = o[i][1];
        }
        __syncthreads();
    }
}

// ---------------------------------------------------------------------------
// Launch
// ---------------------------------------------------------------------------
extern "C" void kernel_launch(void* const* d_in, const int* in_sizes, int n_in,
                              void* d_out, int out_size)
{
    const float* x       = (const float*)d_in[0];
    const float* query   = (const float*)d_in[1];
    const float* key_w   = (const float*)d_in[2];
    const float* key_b   = (const float*)d_in[3];
    const float* query_w = (const float*)d_in[4];
    const float* query_b = (const float*)d_in[5];
    const float* val_w   = (const float*)d_in[6];
    const float* val_b   = (const float*)d_in[7];
    const float* up_w    = (const float*)d_in[8];
    const float* up_b    = (const float*)d_in[9];
    float* out = (float*)d_out;

    float *kbuf, *qbuf, *vbuf, *obuf;
    cudaGetSymbolAddress((void**)&kbuf, g_k);
    cudaGetSymbolAddress((void**)&qbuf, g_q);
    cudaGetSymbolAddress((void**)&vbuf, g_v);
    cudaGetSymbolAddress((void**)&obuf, g_o);

    const dim3 blk(256);
    const dim3 grid_proj((NSP + 127) / 128, COUT / 128, B_);   // (13, 4, 32)
    const dim3 grid_up((NSP + 127) / 128, CIN / 128, B_);      // (13, 8, 32)

    gemm_tf32_kernel<<<grid_proj, blk>>>(key_w,   x,     key_b,   kbuf, COUT, NSP, CIN);
    gemm_tf32_kernel<<<grid_proj, blk>>>(query_w, query, query_b, qbuf, COUT, NSP, CIN);
    gemm_tf32_kernel<<<grid_proj, blk>>>(val_w,   x,     val_b,   vbuf, COUT, NSP, CIN);

    attention_kernel<<<B_ * NHEAD, blk>>>(kbuf, qbuf, vbuf, obuf);

    gemm_tf32_kernel<<<grid_up, blk>>>(up_w, obuf, up_b, out, CIN, NSP, COUT);
}